// round 14
// baseline (speedup 1.0000x reference)
#include <cuda_runtime.h>
#include <cuda_bf16.h>
#include <cstdint>

#define Nn 50000
#define NnPad 50048
#define Ee 600000
#define Gg 512
#define NUM_TILES64 782   // ceil(50000/64)

// ============================================================================
// PTX helpers
// ============================================================================
__device__ __forceinline__ uint32_t smem_to_u32(const void* smem_ptr) {
    uint32_t addr;
    asm("{ .reg .u64 tmp; cvta.to.shared.u64 tmp, %1; cvt.u32.u64 %0, tmp; }"
        : "=r"(addr) : "l"(smem_ptr));
    return addr;
}

#define LDSM_X4(r0, r1, r2, r3, addr) \
    asm volatile("ldmatrix.sync.aligned.m8n8.x4.shared.b16 {%0,%1,%2,%3}, [%4];" \
        : "=r"(r0), "=r"(r1), "=r"(r2), "=r"(r3) : "r"(addr))

#define MMA16816(c, a0, a1, a2, a3, b0, b1) \
    asm volatile("mma.sync.aligned.m16n8k16.row.col.f32.bf16.bf16.f32 " \
        "{%0,%1,%2,%3}, {%4,%5,%6,%7}, {%8,%9}, {%0,%1,%2,%3};" \
        : "+f"((c)[0]), "+f"((c)[1]), "+f"((c)[2]), "+f"((c)[3]) \
        : "r"(a0), "r"(a1), "r"(a2), "r"(a3), "r"(b0), "r"(b1))

// ============================================================================
// Scratch (device globals) — no A buffers; h ping-pong only (~80MB hot < L2)
// ============================================================================
__device__ __align__(16) __nv_bfloat16 d_Wh[3 * 128 * 256];
__device__ __align__(16) __nv_bfloat16 d_Wl[3 * 128 * 256];
__device__ __align__(16) float d_h0[(size_t)NnPad * 128];
__device__ __align__(16) float d_h1[(size_t)NnPad * 128];
__device__ float d_pooled[Gg * 256];
__device__ int   d_csr[Ee];
__device__ int   d_rowptr[Nn + 1];
__device__ int   d_cursor[Nn];
__device__ int   d_degi[Nn];
__device__ int   d_gptr[Gg + 1];
__device__ int   d_is64;

// ============================================================================
// index dtype handling (int64 vs int32)
// ============================================================================
__device__ __forceinline__ int load_idx(const void* p, long long i, int is64) {
    if (is64) return (int)((const long long*)p)[i];
    return ((const int*)p)[i];
}
__global__ void detect_kernel(const void* __restrict__ ei) {
    const long long* p = (const long long*)ei;
    int ok = 1;
    for (int i = 0; i < 64; ++i) {
        long long v = p[i];
        if (v < 0 || v >= (long long)Nn) { ok = 0; break; }
    }
    d_is64 = ok;
}

__global__ void gptr_kernel(const void* __restrict__ batch) {
    int is64 = d_is64;
    int g = threadIdx.x;   // 0..511
    int lo = 0, hi = Nn;
    while (lo < hi) {
        int mid = (lo + hi) >> 1;
        int v = load_idx(batch, mid, is64);
        if (v < g) lo = mid + 1; else hi = mid;
    }
    d_gptr[g] = lo;
    if (g == 0) d_gptr[Gg] = Nn;
}

__global__ void zero_kernel() {
    int i = blockIdx.x * blockDim.x + threadIdx.x;
    int stride = gridDim.x * blockDim.x;
    for (int j = i; j < Nn; j += stride) { d_degi[j] = 0; d_cursor[j] = 0; }
}

__global__ void deg_hist_kernel(const void* __restrict__ ei) {
    int is64 = d_is64;
    int stride = gridDim.x * blockDim.x;
    for (int e = blockIdx.x * blockDim.x + threadIdx.x; e < Ee; e += stride) {
        int dst = load_idx(ei, (long long)Ee + e, is64);
        atomicAdd(&d_degi[dst], 1);
    }
}

// one-block exclusive scan: degi -> rowptr
__global__ void scan_kernel() {
    __shared__ int sh[1024];
    const int SEG = 49;   // 1024*49 = 50176 >= 50001
    int t = threadIdx.x;
    int base = t * SEG;
    int s = 0;
    #pragma unroll 7
    for (int i = 0; i < SEG; ++i) {
        int idx = base + i;
        if (idx < Nn) s += d_degi[idx];
    }
    sh[t] = s;
    __syncthreads();
    for (int off = 1; off < 1024; off <<= 1) {
        int v = (t >= off) ? sh[t - off] : 0;
        __syncthreads();
        sh[t] += v;
        __syncthreads();
    }
    int run = t ? sh[t - 1] : 0;
    #pragma unroll 7
    for (int i = 0; i < SEG; ++i) {
        int idx = base + i;
        if (idx < Nn) { d_rowptr[idx] = run; run += d_degi[idx]; }
        else if (idx == Nn) { d_rowptr[Nn] = run; }
    }
}

__global__ void csr_fill_kernel(const void* __restrict__ ei) {
    int is64 = d_is64;
    int stride = gridDim.x * blockDim.x;
    for (int e = blockIdx.x * blockDim.x + threadIdx.x; e < Ee; e += stride) {
        int src = load_idx(ei, e, is64);
        int dst = load_idx(ei, (long long)Ee + e, is64);
        int pos = d_rowptr[dst] + atomicAdd(&d_cursor[dst], 1);
        d_csr[pos] = src;
    }
}

// ============================================================================
// bf16 hi/lo split helpers
// ============================================================================
__device__ __forceinline__ void split_pack(float a, float b, uint32_t& hi, uint32_t& lo) {
    __nv_bfloat16 ha = __float2bfloat16_rn(a), hb = __float2bfloat16_rn(b);
    __nv_bfloat162 hv; hv.x = ha; hv.y = hb;
    hi = *reinterpret_cast<uint32_t*>(&hv);
    float la = a - __bfloat162float(ha);
    float lb = b - __bfloat162float(hb);
    __nv_bfloat162 lv = __floats2bfloat162_rn(la, lb);
    lo = *reinterpret_cast<uint32_t*>(&lv);
}

// convert weights: Wcat[layer][o][k] = k<128 ? Wl[o][k] : Wr[o][k-128], split hi/lo
__global__ void wprep_kernel(const float* W1l, const float* W1r,
                             const float* W2l, const float* W2r,
                             const float* W3l, const float* W3r) {
    int idx = blockIdx.x * blockDim.x + threadIdx.x;   // over 3*128*256
    if (idx >= 3 * 128 * 256) return;
    int layer = idx / (128 * 256);
    int rem = idx - layer * 128 * 256;
    int o = rem >> 8, k = rem & 255;
    const float* Wl = layer == 0 ? W1l : layer == 1 ? W2l : W3l;
    const float* Wr = layer == 0 ? W1r : layer == 1 ? W2r : W3r;
    float v = (k < 128) ? Wl[o * 128 + k] : Wr[o * 128 + k - 128];
    __nv_bfloat16 hv = __float2bfloat16_rn(v);
    float lvf = v - __bfloat162float(hv);
    d_Wh[idx] = hv;
    d_Wl[idx] = __float2bfloat16_rn(lvf);
}

// ============================================================================
// FUSED layer: aggregation (gather+mean+self) -> SMEM bf16 A tile -> MMA -> h_out
//   64-row tiles, 512 threads (16 warps), 1 CTA/SM persistent.
//   SMEM: Whi 64KB | Wlo 64KB | Ahi 32KB | Alo 32KB | bias 512B = 197120 B
//   A tile layout == W layout: row r (0..63), 16B unit u (0..31),
//   addr = base + r*512 + ((u ^ (r&7))<<4).  Zero cp.async; 2 syncs/tile.
// ============================================================================
#define OFF_WHI  0
#define OFF_WLO  65536
#define OFF_AHI  131072
#define OFF_ALO  163840
#define OFF_BIAS 196608
#define FUSED_SMEM 197120

__global__ __launch_bounds__(512, 1)
void fused_layer(int layer, const float* __restrict__ bias, int do_relu,
                 const float* __restrict__ hin, float* __restrict__ hout)
{
    extern __shared__ char smem[];
    const uint32_t sb = smem_to_u32(smem);
    const int tid = threadIdx.x;
    const int wid = tid >> 5, lane = tid & 31;
    const int wm = wid & 3, wn = wid >> 2;    // GEMM: 4x4 warp grid (16 rows x 32 cols)

    const __nv_bfloat16* __restrict__ WhiG = d_Wh + layer * 32768;
    const __nv_bfloat16* __restrict__ WloG = d_Wl + layer * 32768;
    float* sbias = reinterpret_cast<float*>(smem + OFF_BIAS);

    // ---- load W (hi+lo) into swizzled SMEM: 4096 16B-units each ----
    #pragma unroll
    for (int m = 0; m < 2; ++m) {
        const __nv_bfloat16* srcW = m ? WloG : WhiG;
        char* dstW = smem + (m ? OFF_WLO : OFF_WHI);
        #pragma unroll 4
        for (int j = 0; j < 8; ++j) {
            int idx = tid + j * 512;     // 0..4095 16B units
            int n = idx >> 5, u = idx & 31;
            float4 v = *reinterpret_cast<const float4*>(srcW + n * 256 + u * 8);
            *reinterpret_cast<float4*>(dstW + n * 512 + ((u ^ (n & 7)) << 4)) = v;
        }
    }
    if (tid < 128) sbias[tid] = bias[tid];
    __syncthreads();

    const int uA = lane >> 1;            // 16B unit within agg half (0..15)
    const int subA = (lane & 1) * 8;     // 8B sub-offset

    for (int tile = blockIdx.x; tile < NUM_TILES64; tile += gridDim.x) {
        const int tbase = tile * 64;

        // ================= aggregation phase: warp -> 4 nodes =================
        #pragma unroll 1
        for (int i = 0; i < 4; ++i) {
            const int lr = wid * 4 + i;          // local row 0..63
            const int node = tbase + lr;
            float4 acc = make_float4(0.f, 0.f, 0.f, 0.f);
            float4 self = make_float4(0.f, 0.f, 0.f, 0.f);
            if (node < Nn) {
                const int beg = d_rowptr[node];
                const int end = d_rowptr[node + 1];
                int e = beg;
                #pragma unroll 1
                for (; e + 4 <= end; e += 4) {
                    int s0 = __ldg(&d_csr[e + 0]);
                    int s1 = __ldg(&d_csr[e + 1]);
                    int s2 = __ldg(&d_csr[e + 2]);
                    int s3 = __ldg(&d_csr[e + 3]);
                    float4 v0 = *reinterpret_cast<const float4*>(hin + (size_t)s0 * 128 + lane * 4);
                    float4 v1 = *reinterpret_cast<const float4*>(hin + (size_t)s1 * 128 + lane * 4);
                    float4 v2 = *reinterpret_cast<const float4*>(hin + (size_t)s2 * 128 + lane * 4);
                    float4 v3 = *reinterpret_cast<const float4*>(hin + (size_t)s3 * 128 + lane * 4);
                    acc.x += v0.x + v1.x + v2.x + v3.x;
                    acc.y += v0.y + v1.y + v2.y + v3.y;
                    acc.z += v0.z + v1.z + v2.z + v3.z;
                    acc.w += v0.w + v1.w + v2.w + v3.w;
                }
                #pragma unroll 1
                for (; e < end; ++e) {
                    int s = __ldg(&d_csr[e]);
                    float4 v = *reinterpret_cast<const float4*>(hin + (size_t)s * 128 + lane * 4);
                    acc.x += v.x; acc.y += v.y; acc.z += v.z; acc.w += v.w;
                }
                const int deg = end - beg;
                const float inv = 1.f / (float)(deg > 1 ? deg : 1);
                acc.x *= inv; acc.y *= inv; acc.z *= inv; acc.w *= inv;
                self = *reinterpret_cast<const float4*>(hin + (size_t)node * 128 + lane * 4);
            }
            // store agg -> A cols 0..127 (units 0..15)
            uint32_t h0, l0, h1, l1;
            split_pack(acc.x, acc.y, h0, l0);
            split_pack(acc.z, acc.w, h1, l1);
            {
                uint32_t off = lr * 512 + (((uA) ^ (lr & 7)) << 4) + subA;
                uint2 hh; hh.x = h0; hh.y = h1;
                uint2 ll; ll.x = l0; ll.y = l1;
                *reinterpret_cast<uint2*>(smem + OFF_AHI + off) = hh;
                *reinterpret_cast<uint2*>(smem + OFF_ALO + off) = ll;
            }
            // store self -> A cols 128..255 (units 16..31)
            split_pack(self.x, self.y, h0, l0);
            split_pack(self.z, self.w, h1, l1);
            {
                uint32_t off = lr * 512 + (((16 + uA) ^ (lr & 7)) << 4) + subA;
                uint2 hh; hh.x = h0; hh.y = h1;
                uint2 ll; ll.x = l0; ll.y = l1;
                *reinterpret_cast<uint2*>(smem + OFF_AHI + off) = hh;
                *reinterpret_cast<uint2*>(smem + OFF_ALO + off) = ll;
            }
        }
        __syncthreads();

        // ================= GEMM phase: K=256, 3 products, A SMEM-resident ======
        float acc[16];
        #pragma unroll
        for (int i = 0; i < 16; ++i) acc[i] = 0.f;

        #pragma unroll 4
        for (int ks = 0; ks < 16; ++ks) {
            const int r = wm * 16 + (lane & 15);
            const int kg = ks * 16 + ((lane >> 4) << 3);
            const int u = kg >> 3;
            uint32_t ah[4], al[4];
            {
                uint32_t ad = sb + OFF_AHI + r * 512 + (((u ^ (r & 7))) << 4);
                LDSM_X4(ah[0], ah[1], ah[2], ah[3], ad);
            }
            {
                uint32_t ad = sb + OFF_ALO + r * 512 + (((u ^ (r & 7))) << 4);
                LDSM_X4(al[0], al[1], al[2], al[3], ad);
            }
            #pragma unroll
            for (int bt = 0; bt < 2; ++bt) {
                const int n = wn * 32 + bt * 16 + (lane & 15);
                uint32_t bh0, bh1, bh2, bh3, bl0, bl1, bl2, bl3;
                {
                    uint32_t bd = sb + OFF_WHI + n * 512 + (((u ^ (n & 7))) << 4);
                    LDSM_X4(bh0, bh1, bh2, bh3, bd);
                }
                {
                    uint32_t bd = sb + OFF_WLO + n * 512 + (((u ^ (n & 7))) << 4);
                    LDSM_X4(bl0, bl1, bl2, bl3, bd);
                }
                float* c0 = &acc[(bt * 2 + 0) * 4];
                float* c1 = &acc[(bt * 2 + 1) * 4];
                MMA16816(c0, ah[0], ah[1], ah[2], ah[3], bh0, bh2);   // Ahi*Whi
                MMA16816(c1, ah[0], ah[1], ah[2], ah[3], bh1, bh3);
                MMA16816(c0, al[0], al[1], al[2], al[3], bh0, bh2);   // Alo*Whi
                MMA16816(c1, al[0], al[1], al[2], al[3], bh1, bh3);
                MMA16816(c0, ah[0], ah[1], ah[2], ah[3], bl0, bl2);   // Ahi*Wlo
                MMA16816(c1, ah[0], ah[1], ah[2], ah[3], bl1, bl3);
            }
        }

        // ================= epilogue: bias + relu -> h_out =====================
        const int g = lane >> 2, tg = lane & 3;
        const int r0 = tbase + wm * 16 + g;
        #pragma unroll
        for (int nt = 0; nt < 4; ++nt) {
            const int col = wn * 32 + nt * 8 + tg * 2;
            float2 bb = *reinterpret_cast<const float2*>(&sbias[col]);
            float v0 = acc[nt * 4 + 0] + bb.x;
            float v1 = acc[nt * 4 + 1] + bb.y;
            float v2 = acc[nt * 4 + 2] + bb.x;
            float v3 = acc[nt * 4 + 3] + bb.y;
            if (do_relu) {
                v0 = fmaxf(v0, 0.f); v1 = fmaxf(v1, 0.f);
                v2 = fmaxf(v2, 0.f); v3 = fmaxf(v3, 0.f);
            }
            if (r0 < Nn) {
                float2 o; o.x = v0; o.y = v1;
                *reinterpret_cast<float2*>(hout + (size_t)r0 * 128 + col) = o;
            }
            if (r0 + 8 < Nn) {
                float2 o; o.x = v2; o.y = v3;
                *reinterpret_cast<float2*>(hout + (size_t)(r0 + 8) * 128 + col) = o;
            }
        }
        __syncthreads();   // A smem fully consumed before next tile's agg phase
    }
}

// ============================================================================
// pooling + head
// ============================================================================
__global__ void pool_kernel() {
    int g = blockIdx.x;
    int c = threadIdx.x;              // 128 threads, one per column
    int beg = d_gptr[g], end = d_gptr[g + 1];
    float mx = -3.402823466e38f, sm = 0.f;
    for (int r = beg; r < end; ++r) {
        float v = d_h0[(size_t)r * 128 + c];
        mx = fmaxf(mx, v);
        sm += v;
    }
    int cnt = end - beg;
    d_pooled[g * 256 + c]       = (cnt > 0) ? mx : 0.f;
    d_pooled[g * 256 + 128 + c] = sm / (float)(cnt > 1 ? cnt : 1);
}

__global__ __launch_bounds__(256) void head_kernel(
    const float* __restrict__ Wlin, const float* __restrict__ blin,
    float* __restrict__ out)
{
    __shared__ float p[256];
    int g = blockIdx.x, o = threadIdx.x;
    p[o] = d_pooled[g * 256 + o];
    __syncthreads();
    float acc = blin[o];
    const float4* wr = reinterpret_cast<const float4*>(Wlin + o * 256);
    #pragma unroll 8
    for (int k = 0; k < 64; ++k) {
        float4 w = wr[k];
        float4 pv = *reinterpret_cast<const float4*>(&p[k * 4]);
        acc = fmaf(w.x, pv.x, acc);
        acc = fmaf(w.y, pv.y, acc);
        acc = fmaf(w.z, pv.z, acc);
        acc = fmaf(w.w, pv.w, acc);
    }
    out[g * 256 + o] = acc;
}

// ============================================================================
// launch
// ============================================================================
extern "C" void kernel_launch(void* const* d_in, const int* in_sizes, int n_in,
                              void* d_out, int out_size)
{
    const float* x     = (const float*)d_in[0];
    const void*  ei    = d_in[1];
    const void*  batch = d_in[2];
    const float* W1l = (const float*)d_in[3];
    const float* b1  = (const float*)d_in[4];
    const float* W1r = (const float*)d_in[5];
    const float* W2l = (const float*)d_in[6];
    const float* b2  = (const float*)d_in[7];
    const float* W2r = (const float*)d_in[8];
    const float* W3l = (const float*)d_in[9];
    const float* b3  = (const float*)d_in[10];
    const float* W3r = (const float*)d_in[11];
    const float* Wlin = (const float*)d_in[12];
    const float* blin = (const float*)d_in[13];
    float* out = (float*)d_out;

    cudaFuncSetAttribute(fused_layer, cudaFuncAttributeMaxDynamicSharedMemorySize, FUSED_SMEM);

    detect_kernel<<<1, 1>>>(ei);
    gptr_kernel<<<1, 512>>>(batch);
    zero_kernel<<<98, 512>>>();
    deg_hist_kernel<<<512, 256>>>(ei);
    scan_kernel<<<1, 1024>>>();
    csr_fill_kernel<<<512, 256>>>(ei);
    wprep_kernel<<<384, 256>>>(W1l, W1r, W2l, W2r, W3l, W3r);

    // h0/h1 ping-pong: L1 x->h0, L2 h0->h1, L3 h1->h0
    float* h0 = nullptr; float* h1 = nullptr;
    cudaGetSymbolAddress((void**)&h0, d_h0);
    cudaGetSymbolAddress((void**)&h1, d_h1);

    fused_layer<<<148, 512, FUSED_SMEM>>>(0, b1, 1, x,  h0);
    fused_layer<<<148, 512, FUSED_SMEM>>>(1, b2, 1, h0, h1);
    fused_layer<<<148, 512, FUSED_SMEM>>>(2, b3, 0, h1, h0);

    pool_kernel<<<Gg, 128>>>();
    head_kernel<<<Gg, 256>>>(Wlin, blin, out);
}

// round 15
// speedup vs baseline: 1.1310x; 1.1310x over previous
#include <cuda_runtime.h>
#include <cuda_bf16.h>
#include <cstdint>

#define Nn 50000
#define NnPad 50048
#define Ee 600000
#define Gg 512
#define NUM_TILES64 782   // ceil(50000/64)

// ============================================================================
// PTX helpers
// ============================================================================
__device__ __forceinline__ uint32_t smem_to_u32(const void* smem_ptr) {
    uint32_t addr;
    asm("{ .reg .u64 tmp; cvta.to.shared.u64 tmp, %1; cvt.u32.u64 %0, tmp; }"
        : "=r"(addr) : "l"(smem_ptr));
    return addr;
}

#define LDSM_X4(r0, r1, r2, r3, addr) \
    asm volatile("ldmatrix.sync.aligned.m8n8.x4.shared.b16 {%0,%1,%2,%3}, [%4];" \
        : "=r"(r0), "=r"(r1), "=r"(r2), "=r"(r3) : "r"(addr))

#define MMA16816(c, a0, a1, a2, a3, b0, b1) \
    asm volatile("mma.sync.aligned.m16n8k16.row.col.f32.bf16.bf16.f32 " \
        "{%0,%1,%2,%3}, {%4,%5,%6,%7}, {%8,%9}, {%0,%1,%2,%3};" \
        : "+f"((c)[0]), "+f"((c)[1]), "+f"((c)[2]), "+f"((c)[3]) \
        : "r"(a0), "r"(a1), "r"(a2), "r"(a3), "r"(b0), "r"(b1))

#define CP_ASYNC16(dst_u32, src_ptr) \
    asm volatile("cp.async.cg.shared.global [%0], [%1], 16;" \
        :: "r"(dst_u32), "l"(src_ptr) : "memory")
#define CP_COMMIT() asm volatile("cp.async.commit_group;" ::: "memory")
#define CP_WAIT0()  asm volatile("cp.async.wait_group 0;" ::: "memory")

// ============================================================================
// Scratch (device globals)
// ============================================================================
__device__ __align__(16) __nv_bfloat16 d_Ahi[(size_t)NnPad * 256];
__device__ __align__(16) __nv_bfloat16 d_Alo[(size_t)NnPad * 256];
__device__ __align__(16) __nv_bfloat16 d_Wh[3 * 128 * 256];
__device__ __align__(16) __nv_bfloat16 d_Wl[3 * 128 * 256];
__device__ __align__(16) float d_h[(size_t)NnPad * 128];
__device__ float d_pooled[Gg * 256];
__device__ int   d_csr[Ee];
__device__ int   d_rowptr[Nn + 1];
__device__ int   d_cursor[Nn];
__device__ int   d_degi[Nn];
__device__ int   d_gptr[Gg + 1];
__device__ int   d_is64;

// ============================================================================
// index dtype handling (int64 vs int32)
// ============================================================================
__device__ __forceinline__ int load_idx(const void* p, long long i, int is64) {
    if (is64) return (int)((const long long*)p)[i];
    return ((const int*)p)[i];
}
__global__ void detect_kernel(const void* __restrict__ ei) {
    const long long* p = (const long long*)ei;
    int ok = 1;
    for (int i = 0; i < 64; ++i) {
        long long v = p[i];
        if (v < 0 || v >= (long long)Nn) { ok = 0; break; }
    }
    d_is64 = ok;
}

__global__ void gptr_kernel(const void* __restrict__ batch) {
    int is64 = d_is64;
    int g = threadIdx.x;   // 0..511
    int lo = 0, hi = Nn;
    while (lo < hi) {
        int mid = (lo + hi) >> 1;
        int v = load_idx(batch, mid, is64);
        if (v < g) lo = mid + 1; else hi = mid;
    }
    d_gptr[g] = lo;
    if (g == 0) d_gptr[Gg] = Nn;
}

__global__ void zero_kernel() {
    int i = blockIdx.x * blockDim.x + threadIdx.x;
    int stride = gridDim.x * blockDim.x;
    for (int j = i; j < Nn; j += stride) { d_degi[j] = 0; d_cursor[j] = 0; }
}

__global__ void deg_hist_kernel(const void* __restrict__ ei) {
    int is64 = d_is64;
    int stride = gridDim.x * blockDim.x;
    for (int e = blockIdx.x * blockDim.x + threadIdx.x; e < Ee; e += stride) {
        int dst = load_idx(ei, (long long)Ee + e, is64);
        atomicAdd(&d_degi[dst], 1);
    }
}

// one-block exclusive scan: degi -> rowptr
__global__ void scan_kernel() {
    __shared__ int sh[1024];
    const int SEG = 49;   // 1024*49 = 50176 >= 50001
    int t = threadIdx.x;
    int base = t * SEG;
    int s = 0;
    #pragma unroll 7
    for (int i = 0; i < SEG; ++i) {
        int idx = base + i;
        if (idx < Nn) s += d_degi[idx];
    }
    sh[t] = s;
    __syncthreads();
    for (int off = 1; off < 1024; off <<= 1) {
        int v = (t >= off) ? sh[t - off] : 0;
        __syncthreads();
        sh[t] += v;
        __syncthreads();
    }
    int run = t ? sh[t - 1] : 0;
    #pragma unroll 7
    for (int i = 0; i < SEG; ++i) {
        int idx = base + i;
        if (idx < Nn) { d_rowptr[idx] = run; run += d_degi[idx]; }
        else if (idx == Nn) { d_rowptr[Nn] = run; }
    }
}

__global__ void csr_fill_kernel(const void* __restrict__ ei) {
    int is64 = d_is64;
    int stride = gridDim.x * blockDim.x;
    for (int e = blockIdx.x * blockDim.x + threadIdx.x; e < Ee; e += stride) {
        int src = load_idx(ei, e, is64);
        int dst = load_idx(ei, (long long)Ee + e, is64);
        int pos = d_rowptr[dst] + atomicAdd(&d_cursor[dst], 1);
        d_csr[pos] = src;
    }
}

// ============================================================================
// bf16 hi/lo split helpers
// ============================================================================
__device__ __forceinline__ void split_pack(float a, float b, uint32_t& hi, uint32_t& lo) {
    __nv_bfloat16 ha = __float2bfloat16_rn(a), hb = __float2bfloat16_rn(b);
    __nv_bfloat162 hv; hv.x = ha; hv.y = hb;
    hi = *reinterpret_cast<uint32_t*>(&hv);
    float la = a - __bfloat162float(ha);
    float lb = b - __bfloat162float(hb);
    __nv_bfloat162 lv = __floats2bfloat162_rn(la, lb);
    lo = *reinterpret_cast<uint32_t*>(&lv);
}

// convert weights: Wcat[layer][o][k] = k<128 ? Wl[o][k] : Wr[o][k-128], split hi/lo
__global__ void wprep_kernel(const float* W1l, const float* W1r,
                             const float* W2l, const float* W2r,
                             const float* W3l, const float* W3r) {
    int idx = blockIdx.x * blockDim.x + threadIdx.x;   // over 3*128*256
    if (idx >= 3 * 128 * 256) return;
    int layer = idx / (128 * 256);
    int rem = idx - layer * 128 * 256;
    int o = rem >> 8, k = rem & 255;
    const float* Wl = layer == 0 ? W1l : layer == 1 ? W2l : W3l;
    const float* Wr = layer == 0 ? W1r : layer == 1 ? W2r : W3r;
    float v = (k < 128) ? Wl[o * 128 + k] : Wr[o * 128 + k - 128];
    __nv_bfloat16 hv = __float2bfloat16_rn(v);
    float lvf = v - __bfloat162float(hv);
    d_Wh[idx] = hv;
    d_Wl[idx] = __float2bfloat16_rn(lvf);
}

// convert x into A cols 128..255 (self features for layer 1)
__global__ void xconv_kernel(const float* __restrict__ x) {
    int idx = blockIdx.x * blockDim.x + threadIdx.x;   // Nn*32
    if (idx >= Nn * 32) return;
    int n = idx >> 5, c4 = idx & 31;
    float4 v = *reinterpret_cast<const float4*>(x + (size_t)n * 128 + c4 * 4);
    uint32_t h0, l0, h1, l1;
    split_pack(v.x, v.y, h0, l0);
    split_pack(v.z, v.w, h1, l1);
    size_t off = (size_t)n * 256 + 128 + c4 * 4;
    uint2 hh; hh.x = h0; hh.y = h1;
    uint2 ll; ll.x = l0; ll.y = l1;
    *reinterpret_cast<uint2*>(&d_Ahi[off]) = hh;
    *reinterpret_cast<uint2*>(&d_Alo[off]) = ll;
}

// ============================================================================
// mean aggregation: warp per node, cp.async-pipelined gather (R13-exact)
// ============================================================================
__global__ __launch_bounds__(256, 8) void agg_kernel(
    const float* __restrict__ x, int usex)
{
    __shared__ __align__(16) char buf[8][4][512];
    const float* __restrict__ src = usex ? x : d_h;
    const int warp = (blockIdx.x * blockDim.x + threadIdx.x) >> 5;   // exactly Nn warps
    const int wl = threadIdx.x >> 5;
    const int lane = threadIdx.x & 31;
    const int beg = d_rowptr[warp];
    const int end = d_rowptr[warp + 1];
    const uint32_t sbase = smem_to_u32(&buf[wl][0][0]) + lane * 16;

    float4 acc = make_float4(0.f, 0.f, 0.f, 0.f);
    int e = beg;
    #pragma unroll 1
    while (e < end) {
        const int n = (end - e) < 4 ? (end - e) : 4;
        #pragma unroll
        for (int d = 0; d < 4; ++d) {
            if (d < n) {
                int s = d_csr[e + d];
                CP_ASYNC16(sbase + d * 512,
                           reinterpret_cast<const char*>(src + (size_t)s * 128) + lane * 16);
            }
        }
        CP_COMMIT();
        CP_WAIT0();
        #pragma unroll
        for (int d = 0; d < 4; ++d) {
            if (d < n) {
                float4 v = *reinterpret_cast<const float4*>(&buf[wl][d][lane * 16]);
                acc.x += v.x; acc.y += v.y; acc.z += v.z; acc.w += v.w;
            }
        }
        e += n;
    }

    const int deg = end - beg;
    const float inv = 1.f / (float)(deg > 1 ? deg : 1);
    acc.x *= inv; acc.y *= inv; acc.z *= inv; acc.w *= inv;
    uint32_t h0, l0, h1, l1;
    split_pack(acc.x, acc.y, h0, l0);
    split_pack(acc.z, acc.w, h1, l1);
    size_t off = (size_t)warp * 256 + lane * 4;
    uint2 hh; hh.x = h0; hh.y = h1;
    uint2 ll; ll.x = l0; ll.y = l1;
    *reinterpret_cast<uint2*>(d_Ahi + off) = hh;
    *reinterpret_cast<uint2*>(d_Alo + off) = ll;
}

// ============================================================================
// Tensor-core GEMM — 64-row tiles, A tile FULLY SMEM-resident, barrier-free
// 16-kstep MMA sweep (2 syncs/tile). 512 threads, 4x4 warp grid (16r x 32c).
// Next tile's A prefetch overlaps the epilogue's global writes.
// SMEM: Whi 64KB | Wlo 64KB | Ahi 32KB | Alo 32KB | bias 512B = 197120 B
// A tile layout == W layout: row r (0..63), 16B unit u (0..31),
//   addr = base + r*512 + ((u ^ (r&7))<<4)
// ============================================================================
#define OFF_WHI  0
#define OFF_WLO  65536
#define OFF_AHI  131072
#define OFF_ALO  163840
#define OFF_BIAS 196608
#define GEMM_SMEM 197120

__device__ __forceinline__ void prefetch_a64(size_t rowBase, uint32_t sb, int tid) {
    // 64 rows x 32 units, hi then lo: 2048 units each, 512 threads x 4 iters
    #pragma unroll
    for (int j = 0; j < 4; ++j) {
        int idx = tid + j * 512;             // 0..2047
        int r = idx >> 5, u = idx & 31;
        uint32_t doff = r * 512 + ((u ^ (r & 7)) << 4);
        CP_ASYNC16(sb + OFF_AHI + doff, d_Ahi + (rowBase + r) * 256 + u * 8);
        CP_ASYNC16(sb + OFF_ALO + doff, d_Alo + (rowBase + r) * 256 + u * 8);
    }
}

__global__ __launch_bounds__(512, 1)
void sage_mma_gemm64(int layer, const float* __restrict__ bias,
                     int do_relu, int writeNext)
{
    extern __shared__ char smem[];
    const uint32_t sb = smem_to_u32(smem);
    const int tid = threadIdx.x;
    const int wid = tid >> 5, lane = tid & 31;
    const int wm = wid & 3, wn = wid >> 2;    // 4x4 warp grid

    const __nv_bfloat16* __restrict__ WhiG = d_Wh + layer * 32768;
    const __nv_bfloat16* __restrict__ WloG = d_Wl + layer * 32768;
    float* sbias = reinterpret_cast<float*>(smem + OFF_BIAS);

    // ---- load W (hi+lo) into swizzled SMEM: 4096 16B-units each ----
    #pragma unroll
    for (int m = 0; m < 2; ++m) {
        const __nv_bfloat16* srcW = m ? WloG : WhiG;
        char* dstW = smem + (m ? OFF_WLO : OFF_WHI);
        #pragma unroll 4
        for (int j = 0; j < 8; ++j) {
            int idx = tid + j * 512;     // 0..4095 16B units
            int n = idx >> 5, u = idx & 31;
            float4 v = *reinterpret_cast<const float4*>(srcW + n * 256 + u * 8);
            *reinterpret_cast<float4*>(dstW + n * 512 + ((u ^ (n & 7)) << 4)) = v;
        }
    }
    if (tid < 128) sbias[tid] = bias[tid];

    // prefetch first tile's A while W settles
    prefetch_a64((size_t)blockIdx.x * 64, sb, tid);
    CP_COMMIT();
    __syncthreads();

    for (int tile = blockIdx.x; tile < NUM_TILES64; tile += gridDim.x) {
        const int tbase = tile * 64;

        CP_WAIT0();
        __syncthreads();          // whole A tile visible to all warps

        // ---- barrier-free MMA sweep: K=256 (16 ksteps), 3 products ----
        float acc[16];
        #pragma unroll
        for (int i = 0; i < 16; ++i) acc[i] = 0.f;

        #pragma unroll 4
        for (int ks = 0; ks < 16; ++ks) {
            const int r = wm * 16 + (lane & 15);
            const int kg = ks * 16 + ((lane >> 4) << 3);
            const int u = kg >> 3;
            uint32_t ah[4], al[4];
            {
                uint32_t ad = sb + OFF_AHI + r * 512 + (((u ^ (r & 7))) << 4);
                LDSM_X4(ah[0], ah[1], ah[2], ah[3], ad);
            }
            {
                uint32_t ad = sb + OFF_ALO + r * 512 + (((u ^ (r & 7))) << 4);
                LDSM_X4(al[0], al[1], al[2], al[3], ad);
            }
            #pragma unroll
            for (int bt = 0; bt < 2; ++bt) {
                const int n = wn * 32 + bt * 16 + (lane & 15);
                uint32_t bh0, bh1, bh2, bh3, bl0, bl1, bl2, bl3;
                {
                    uint32_t bd = sb + OFF_WHI + n * 512 + (((u ^ (n & 7))) << 4);
                    LDSM_X4(bh0, bh1, bh2, bh3, bd);
                }
                {
                    uint32_t bd = sb + OFF_WLO + n * 512 + (((u ^ (n & 7))) << 4);
                    LDSM_X4(bl0, bl1, bl2, bl3, bd);
                }
                float* c0 = &acc[(bt * 2 + 0) * 4];
                float* c1 = &acc[(bt * 2 + 1) * 4];
                MMA16816(c0, ah[0], ah[1], ah[2], ah[3], bh0, bh2);   // Ahi*Whi
                MMA16816(c1, ah[0], ah[1], ah[2], ah[3], bh1, bh3);
                MMA16816(c0, al[0], al[1], al[2], al[3], bh0, bh2);   // Alo*Whi
                MMA16816(c1, al[0], al[1], al[2], al[3], bh1, bh3);
                MMA16816(c0, ah[0], ah[1], ah[2], ah[3], bl0, bl2);   // Ahi*Wlo
                MMA16816(c1, ah[0], ah[1], ah[2], ah[3], bl1, bl3);
            }
        }
        __syncthreads();          // all warps done reading A smem

        // ---- overlap: issue next tile's A load before epilogue writes ----
        {
            int nxt = tile + gridDim.x;
            if (nxt < NUM_TILES64) prefetch_a64((size_t)nxt * 64, sb, tid);
            CP_COMMIT();          // one group per iteration (possibly empty)
        }

        // ---- epilogue: bias + relu; fp32 h + in-place bf16 A cols 128..255 ----
        const int g = lane >> 2, tg = lane & 3;
        const int r0 = tbase + wm * 16 + g;
        #pragma unroll
        for (int nt = 0; nt < 4; ++nt) {
            const int col = wn * 32 + nt * 8 + tg * 2;
            float2 bb = *reinterpret_cast<const float2*>(&sbias[col]);
            float v0 = acc[nt * 4 + 0] + bb.x;
            float v1 = acc[nt * 4 + 1] + bb.y;
            float v2 = acc[nt * 4 + 2] + bb.x;
            float v3 = acc[nt * 4 + 3] + bb.y;
            if (do_relu) {
                v0 = fmaxf(v0, 0.f); v1 = fmaxf(v1, 0.f);
                v2 = fmaxf(v2, 0.f); v3 = fmaxf(v3, 0.f);
            }
            if (r0 < Nn) {
                float2 o; o.x = v0; o.y = v1;
                *reinterpret_cast<float2*>(d_h + (size_t)r0 * 128 + col) = o;
                if (writeNext) {
                    uint32_t hh, ll;
                    split_pack(v0, v1, hh, ll);
                    size_t off = (size_t)r0 * 256 + 128 + col;
                    *reinterpret_cast<uint32_t*>(d_Ahi + off) = hh;
                    *reinterpret_cast<uint32_t*>(d_Alo + off) = ll;
                }
            }
            if (r0 + 8 < Nn) {
                float2 o; o.x = v2; o.y = v3;
                *reinterpret_cast<float2*>(d_h + (size_t)(r0 + 8) * 128 + col) = o;
                if (writeNext) {
                    uint32_t hh, ll;
                    split_pack(v2, v3, hh, ll);
                    size_t off = (size_t)(r0 + 8) * 256 + 128 + col;
                    *reinterpret_cast<uint32_t*>(d_Ahi + off) = hh;
                    *reinterpret_cast<uint32_t*>(d_Alo + off) = ll;
                }
            }
        }
    }
}

// ============================================================================
// pooling (256 threads, 2-way row split) + head
// ============================================================================
__global__ __launch_bounds__(256) void pool_kernel() {
    __shared__ float s1[256], s2[256];
    int g = blockIdx.x;
    int c = threadIdx.x & 127, hf = threadIdx.x >> 7;
    int beg = d_gptr[g], end = d_gptr[g + 1];
    float mx = -3.402823466e38f, sm = 0.f;
    #pragma unroll 1
    for (int r = beg + hf; r < end; r += 2) {
        float v = d_h[(size_t)r * 128 + c];
        mx = fmaxf(mx, v);
        sm += v;
    }
    s1[threadIdx.x] = mx; s2[threadIdx.x] = sm;
    __syncthreads();
    if (hf == 0) {
        mx = fmaxf(mx, s1[c + 128]);
        sm += s2[c + 128];
        int cnt = end - beg;
        d_pooled[g * 256 + c]       = (cnt > 0) ? mx : 0.f;
        d_pooled[g * 256 + 128 + c] = sm / (float)(cnt > 1 ? cnt : 1);
    }
}

__global__ __launch_bounds__(256) void head_kernel(
    const float* __restrict__ Wlin, const float* __restrict__ blin,
    float* __restrict__ out)
{
    __shared__ float p[256];
    int g = blockIdx.x, o = threadIdx.x;
    p[o] = d_pooled[g * 256 + o];
    __syncthreads();
    float acc = blin[o];
    const float4* wr = reinterpret_cast<const float4*>(Wlin + o * 256);
    #pragma unroll 8
    for (int k = 0; k < 64; ++k) {
        float4 w = wr[k];
        float4 pv = *reinterpret_cast<const float4*>(&p[k * 4]);
        acc = fmaf(w.x, pv.x, acc);
        acc = fmaf(w.y, pv.y, acc);
        acc = fmaf(w.z, pv.z, acc);
        acc = fmaf(w.w, pv.w, acc);
    }
    out[g * 256 + o] = acc;
}

// ============================================================================
// launch — R13 sequence with the 64-row GEMM
// ============================================================================
extern "C" void kernel_launch(void* const* d_in, const int* in_sizes, int n_in,
                              void* d_out, int out_size)
{
    const float* x     = (const float*)d_in[0];
    const void*  ei    = d_in[1];
    const void*  batch = d_in[2];
    const float* W1l = (const float*)d_in[3];
    const float* b1  = (const float*)d_in[4];
    const float* W1r = (const float*)d_in[5];
    const float* W2l = (const float*)d_in[6];
    const float* b2  = (const float*)d_in[7];
    const float* W2r = (const float*)d_in[8];
    const float* W3l = (const float*)d_in[9];
    const float* b3  = (const float*)d_in[10];
    const float* W3r = (const float*)d_in[11];
    const float* Wlin = (const float*)d_in[12];
    const float* blin = (const float*)d_in[13];
    float* out = (float*)d_out;

    cudaFuncSetAttribute(sage_mma_gemm64, cudaFuncAttributeMaxDynamicSharedMemorySize, GEMM_SMEM);

    detect_kernel<<<1, 1>>>(ei);
    gptr_kernel<<<1, 512>>>(batch);
    zero_kernel<<<98, 512>>>();
    deg_hist_kernel<<<512, 256>>>(ei);
    scan_kernel<<<1, 1024>>>();
    csr_fill_kernel<<<512, 256>>>(ei);

    wprep_kernel<<<384, 256>>>(W1l, W1r, W2l, W2r, W3l, W3r);
    xconv_kernel<<<6250, 256>>>(x);

    const int aggBlocks = (Nn * 32 + 255) / 256;   // warp per node, exactly Nn warps

    // layer 1: agg(x) -> A cols 0..127; gemm reads A, writes h + A cols 128..255 in place
    agg_kernel<<<aggBlocks, 256>>>(x, 1);
    sage_mma_gemm64<<<148, 512, GEMM_SMEM>>>(0, b1, 1, 1);
    // layer 2
    agg_kernel<<<aggBlocks, 256>>>(nullptr, 0);
    sage_mma_gemm64<<<148, 512, GEMM_SMEM>>>(1, b2, 1, 1);
    // layer 3 (no relu, no writeNext)
    agg_kernel<<<aggBlocks, 256>>>(nullptr, 0);
    sage_mma_gemm64<<<148, 512, GEMM_SMEM>>>(2, b3, 0, 0);

    pool_kernel<<<Gg, 256>>>();
    head_kernel<<<Gg, 256>>>(Wlin, blin, out);
}